// round 14
// baseline (speedup 1.0000x reference)
#include <cuda_runtime.h>
#include <cuda_fp16.h>
#include <cstddef>
#include <cstdint>

// Problem constants
#define NB 8
#define NC 512
#define NH 64
#define NW 64
#define NCQ 64
#define HWP 4096   // NH*NW
#define KDIM 512

// Scratch (statically allocated device globals; no cudaMalloc allowed)
__device__ float  g_q  [NB * NCQ * HWP];
__device__ float  g_k  [NB * NCQ * HWP];
__device__ __half g_v2h[NB * NC  * HWP];        // 32 MB
__device__ __half g_v1h[NB * NC  * HWP];        // 32 MB
__device__ float  g_att [NB * HWP * 128];       // fp32 energies
__device__ __half g_atth[NB * HWP * 128];       // fp16 softmax output
__device__ __half g_outw[2 * NB * NC * HWP];    // 67 MB: aggW partial sums

__device__ __forceinline__ uint32_t pack_h2(float a, float b) {
    __half2 h = __floats2half2_rn(a, b);
    return *reinterpret_cast<uint32_t*>(&h);
}

__device__ __forceinline__ void mma_f16(float& d0, float& d1, float& d2, float& d3,
                                        uint32_t a0, uint32_t a1, uint32_t a2, uint32_t a3,
                                        uint32_t b0, uint32_t b1) {
    asm volatile(
        "mma.sync.aligned.m16n8k16.row.col.f32.f16.f16.f32 "
        "{%0,%1,%2,%3}, {%4,%5,%6,%7}, {%8,%9}, {%0,%1,%2,%3};"
        : "+f"(d0), "+f"(d1), "+f"(d2), "+f"(d3)
        : "r"(a0), "r"(a1), "r"(a2), "r"(a3), "r"(b0), "r"(b1));
}

__device__ __forceinline__ void cp_async16(void* smem_dst, const void* gsrc) {
    uint32_t d = (uint32_t)__cvta_generic_to_shared(smem_dst);
    asm volatile("cp.async.cg.shared.global [%0], [%1], 16;\n" :: "r"(d), "l"(gsrc));
}
#define CP_COMMIT() asm volatile("cp.async.commit_group;\n" ::: "memory")
#define CP_WAIT0()  asm volatile("cp.async.wait_group 0;\n" ::: "memory")

// ---------------------------------------------------------------------------
// gemm_all (unchanged): all projections, fp16 mma.
// ---------------------------------------------------------------------------
__global__ void __launch_bounds__(256)
gemm_all(const float* __restrict__ vw, const float* __restrict__ vb,
         const float* __restrict__ qw, const float* __restrict__ qb,
         const float* __restrict__ kw, const float* __restrict__ kb,
         const float* __restrict__ x2, const float* __restrict__ x1,
         __half* __restrict__ gv2, __half* __restrict__ gv1,
         float* __restrict__ gq,  float* __restrict__ gk)
{
    constexpr int NKT = KDIM / 32;

    __shared__ alignas(16) uint32_t As2[2][16][132];
    __shared__ alignas(16) uint32_t Bs2[2][16][136];

    const int t = threadIdx.x;
    const int z = blockIdx.z;
    const bool qkm = (z >= 16);
    if (qkm && blockIdx.y != 0) return;
    const int b = qkm ? (z - 16) : (z & 7);
    const int s = qkm ? 0 : (z >> 3);
    const int m0 = qkm ? 0 : blockIdx.y * 128;
    const int n0 = blockIdx.x * 128;

    const float* Xb = (qkm ? x2 : (s ? x1 : x2)) + (size_t)b * KDIM * HWP + n0;

    const int warp = t >> 5, lane = t & 31;
    const int gid = lane >> 2, tig = lane & 3;
    const int wm = warp >> 1, wn = warp & 1;

    float acc[2][8][4];
    #pragma unroll
    for (int mi = 0; mi < 2; mi++)
        #pragma unroll
        for (int ni = 0; ni < 8; ni++)
            #pragma unroll
            for (int r = 0; r < 4; r++) acc[mi][ni][r] = 0.f;

    float4 pb[2][2];
    float4 pa[4];

    auto loadA = [&](int kt) {
        #pragma unroll
        for (int i = 0; i < 4; i++) {
            int fa = t + i * 256;
            int row = fa >> 3, c4 = fa & 7;
            const float* src;
            if (qkm) {
                src = (row < 64) ? (qw + (size_t)row * KDIM)
                                 : (kw + (size_t)(row - 64) * KDIM);
            } else {
                src = vw + (size_t)(m0 + row) * KDIM;
            }
            pa[i] = *reinterpret_cast<const float4*>(src + kt * 32 + c4 * 4);
        }
    };
    auto storeA = [&](int buf) {
        #pragma unroll
        for (int i = 0; i < 4; i++) {
            int fa = t + i * 256;
            int row = fa >> 3, c4 = fa & 7;
            As2[buf][2 * c4    ][row] = pack_h2(pa[i].x, pa[i].y);
            As2[buf][2 * c4 + 1][row] = pack_h2(pa[i].z, pa[i].w);
        }
    };
    auto loadB = [&](int kt) {
        #pragma unroll
        for (int i = 0; i < 2; i++) {
            int fb = t + i * 256;
            int k2 = fb >> 5, n4 = fb & 31;
            const float* base = Xb + (size_t)(kt * 32 + 2 * k2) * HWP + n4 * 4;
            pb[i][0] = *reinterpret_cast<const float4*>(base);
            pb[i][1] = *reinterpret_cast<const float4*>(base + HWP);
        }
    };
    auto storeB = [&](int buf) {
        #pragma unroll
        for (int i = 0; i < 2; i++) {
            int fb = t + i * 256;
            int k2 = fb >> 5, n4 = fb & 31;
            uint4 u;
            u.x = pack_h2(pb[i][0].x, pb[i][1].x);
            u.y = pack_h2(pb[i][0].y, pb[i][1].y);
            u.z = pack_h2(pb[i][0].z, pb[i][1].z);
            u.w = pack_h2(pb[i][0].w, pb[i][1].w);
            *reinterpret_cast<uint4*>(&Bs2[buf][k2][n4 * 4]) = u;
        }
    };

    loadA(0); storeA(0);
    loadB(0); storeB(0);
    __syncthreads();

    for (int kt = 0; kt < NKT; kt++) {
        const int cur = kt & 1;
        if (kt + 1 < NKT) { loadA(kt + 1); loadB(kt + 1); }

        #pragma unroll
        for (int ks = 0; ks < 2; ks++) {
            const int kr = ks * 8;
            uint32_t af[2][4];
            #pragma unroll
            for (int mi = 0; mi < 2; mi++) {
                int m = wm * 32 + mi * 16;
                af[mi][0] = As2[cur][kr + tig    ][m + gid];
                af[mi][1] = As2[cur][kr + tig    ][m + gid + 8];
                af[mi][2] = As2[cur][kr + tig + 4][m + gid];
                af[mi][3] = As2[cur][kr + tig + 4][m + gid + 8];
            }
            #pragma unroll
            for (int ni = 0; ni < 8; ni++) {
                int n = wn * 64 + ni * 8 + gid;
                uint32_t b0 = Bs2[cur][kr + tig    ][n];
                uint32_t b1 = Bs2[cur][kr + tig + 4][n];
                #pragma unroll
                for (int mi = 0; mi < 2; mi++)
                    mma_f16(acc[mi][ni][0], acc[mi][ni][1], acc[mi][ni][2], acc[mi][ni][3],
                            af[mi][0], af[mi][1], af[mi][2], af[mi][3], b0, b1);
            }
        }

        if (kt + 1 < NKT) {
            __syncthreads();
            storeA(cur ^ 1); storeB(cur ^ 1);
            __syncthreads();
        }
    }

    #pragma unroll
    for (int mi = 0; mi < 2; mi++) {
        int ml = wm * 32 + mi * 16 + gid;
        #pragma unroll
        for (int half = 0; half < 2; half++) {
            int m = m0 + ml + half * 8;
            if (qkm) {
                float bv;
                float* obase;
                if (m < 64) { bv = qb[m];      obase = gq + ((size_t)b * 64 + m)        * HWP; }
                else        { bv = kb[m - 64]; obase = gk + ((size_t)b * 64 + (m - 64)) * HWP; }
                #pragma unroll
                for (int ni = 0; ni < 8; ni++) {
                    int n = n0 + wn * 64 + ni * 8 + tig * 2;
                    float2 o;
                    o.x = acc[mi][ni][half * 2 + 0] + bv;
                    o.y = acc[mi][ni][half * 2 + 1] + bv;
                    *reinterpret_cast<float2*>(obase + n) = o;
                }
            } else {
                float bv = vb[m];
                __half* O = s ? gv1 : gv2;
                __half* obase = O + ((size_t)b * NC + m) * HWP;
                #pragma unroll
                for (int ni = 0; ni < 8; ni++) {
                    int n = n0 + wn * 64 + ni * 8 + tig * 2;
                    *reinterpret_cast<uint32_t*>(obase + n) =
                        pack_h2(acc[mi][ni][half * 2 + 0] + bv,
                                acc[mi][ni][half * 2 + 1] + bv);
                }
            }
        }
    }
}

// ---------------------------------------------------------------------------
// energy_HW (unchanged)
// ---------------------------------------------------------------------------
__global__ void energy_HW(const float* __restrict__ q,
                          const float* __restrict__ k,
                          float* __restrict__ att)
{
    __shared__ float Qs[64][65];
    __shared__ float Ks[64][65];
    const int t = threadIdx.x;
    const int b = blockIdx.z;
    const int tx = t & 15, ty = t >> 4;

    if (blockIdx.y == 0) {
        const int w = blockIdx.x;
        #pragma unroll
        for (int i = 0; i < 16; i++) {
            int idx = t + i * 256;
            int c = idx >> 6, h = idx & 63;
            size_t g = ((size_t)(b * NCQ + c) * NH + h) * NW + w;
            Qs[c][h] = q[g];
            Ks[c][h] = k[g];
        }
        __syncthreads();
        float acc[4][4];
        #pragma unroll
        for (int i = 0; i < 4; i++)
            #pragma unroll
            for (int j = 0; j < 4; j++) acc[i][j] = 0.f;
        for (int c = 0; c < 64; c++) {
            float qa[4], kb[4];
            #pragma unroll
            for (int i = 0; i < 4; i++) qa[i] = Qs[c][ty * 4 + i];
            #pragma unroll
            for (int j = 0; j < 4; j++) kb[j] = Ks[c][tx * 4 + j];
            #pragma unroll
            for (int i = 0; i < 4; i++)
                #pragma unroll
                for (int j = 0; j < 4; j++) acc[i][j] += qa[i] * kb[j];
        }
        #pragma unroll
        for (int i = 0; i < 4; i++) {
            int h = ty * 4 + i;
            float4 o = {acc[i][0], acc[i][1], acc[i][2], acc[i][3]};
            *reinterpret_cast<float4*>(&att[((size_t)(b * NH + h) * NW + w) * 128 + tx * 4]) = o;
        }
    } else {
        const int h = blockIdx.x;
        #pragma unroll
        for (int i = 0; i < 16; i++) {
            int idx = t + i * 256;
            int c = idx >> 6, w = idx & 63;
            size_t g = ((size_t)(b * NCQ + c) * NH + h) * NW + w;
            Qs[c][w] = q[g];
            Ks[c][w] = k[g];
        }
        __syncthreads();
        float acc[4][4];
        #pragma unroll
        for (int i = 0; i < 4; i++)
            #pragma unroll
            for (int j = 0; j < 4; j++) acc[i][j] = 0.f;
        for (int c = 0; c < 64; c++) {
            float qa[4], kb[4];
            #pragma unroll
            for (int i = 0; i < 4; i++) qa[i] = Qs[c][ty * 4 + i];
            #pragma unroll
            for (int j = 0; j < 4; j++) kb[j] = Ks[c][tx * 4 + j];
            #pragma unroll
            for (int i = 0; i < 4; i++)
                #pragma unroll
                for (int j = 0; j < 4; j++) acc[i][j] += qa[i] * kb[j];
        }
        #pragma unroll
        for (int i = 0; i < 4; i++) {
            int w = ty * 4 + i;
            float4 o = {acc[i][0], acc[i][1], acc[i][2], acc[i][3]};
            *reinterpret_cast<float4*>(&att[((size_t)(b * NH + h) * NW + w) * 128 + 64 + tx * 4]) = o;
        }
    }
}

// ---------------------------------------------------------------------------
// softmax: fp32 in -> fp16 out (unchanged)
// ---------------------------------------------------------------------------
__global__ void softmax_kernel(const float* __restrict__ att,
                               __half* __restrict__ atth)
{
    int gwarp = (blockIdx.x * blockDim.x + threadIdx.x) >> 5;
    int lane  = threadIdx.x & 31;
    if (gwarp >= NB * HWP) return;
    const float4* row = reinterpret_cast<const float4*>(att) + (size_t)gwarp * 32;
    float4 v = row[lane];
    float m = fmaxf(fmaxf(v.x, v.y), fmaxf(v.z, v.w));
    #pragma unroll
    for (int o = 16; o > 0; o >>= 1) m = fmaxf(m, __shfl_xor_sync(0xFFFFFFFFu, m, o));
    v.x = __expf(v.x - m); v.y = __expf(v.y - m);
    v.z = __expf(v.z - m); v.w = __expf(v.w - m);
    float s = v.x + v.y + v.z + v.w;
    #pragma unroll
    for (int o = 16; o > 0; o >>= 1) s += __shfl_xor_sync(0xFFFFFFFFu, s, o);
    float r = 1.0f / s;
    uint2 o;
    o.x = pack_h2(v.x * r, v.y * r);
    o.y = pack_h2(v.z * r, v.w * r);
    *(reinterpret_cast<uint2*>(atth + (size_t)gwarp * 128) + lane) = o;
}

// ---------------------------------------------------------------------------
// aggW_f16 v6 (runs FIRST now): writes partial sums to fp16 outW (no y RMW).
//   outW[s][b][c][h][w] = sum_W' V[c,h,W'] * attW[h,w,W']
// R13 structure: c=128/block, 512 threads, 16 warps = mi(4 w-tiles) x nq(4 c32).
// ---------------------------------------------------------------------------
__global__ void __launch_bounds__(512)
aggW_f16(const __half* __restrict__ v2, const __half* __restrict__ v1,
         const __half* __restrict__ atth, __half* __restrict__ outw)
{
    __shared__ alignas(16) uint32_t Ast[64 * 36];    // att W-half [w][k2]
    __shared__ alignas(16) uint32_t Vst[128 * 36];   // V rows [c][k2]

    const int t  = threadIdx.x;
    const int h  = blockIdx.x;
    const int cs = blockIdx.y;         // s*4 + cc
    const int b  = blockIdx.z;
    const int s  = cs >> 2;
    const int cBase = (cs & 3) * 128;

    const __half* v = s ? v1 : v2;
    __half* od = outw + (size_t)s * NB * NC * HWP;

    {
        int f = t;
        int r = f >> 3, q8 = f & 7;
        cp_async16(Ast + r * 36 + q8 * 4,
                   atth + (((size_t)(b * NH + h) * NW) + r) * 128 + 64 + q8 * 8);
    }
    #pragma unroll
    for (int i = 0; i < 2; i++) {
        int f = t + i * 512;
        int r = f >> 3, q8 = f & 7;
        cp_async16(Vst + r * 36 + q8 * 4,
                   v + (((size_t)(b * NC + cBase + r) * NH) + h) * NW + q8 * 8);
    }
    CP_COMMIT();
    CP_WAIT0();
    __syncthreads();

    const int warp = t >> 5, lane = t & 31;
    const int gid = lane >> 2, tig = lane & 3;
    const int mi = warp >> 2;      // w-tile (m16)
    const int nq = warp & 3;       // c32 quarter

    float acc[4][4];
    #pragma unroll
    for (int ni = 0; ni < 4; ni++)
        #pragma unroll
        for (int r = 0; r < 4; r++) acc[ni][r] = 0.f;

    #pragma unroll
    for (int k = 0; k < 4; k++) {
        const int kk2 = k * 8;
        const int m = mi * 16;
        uint32_t a0 = Ast[(m + gid    ) * 36 + kk2 + tig    ];
        uint32_t a1 = Ast[(m + gid + 8) * 36 + kk2 + tig    ];
        uint32_t a2 = Ast[(m + gid    ) * 36 + kk2 + tig + 4];
        uint32_t a3 = Ast[(m + gid + 8) * 36 + kk2 + tig + 4];
        #pragma unroll
        for (int ni = 0; ni < 4; ni++) {
            int n = nq * 32 + ni * 8 + gid;
            uint32_t b0 = Vst[n * 36 + kk2 + tig    ];
            uint32_t b1 = Vst[n * 36 + kk2 + tig + 4];
            mma_f16(acc[ni][0], acc[ni][1], acc[ni][2], acc[ni][3],
                    a0, a1, a2, a3, b0, b1);
        }
    }

    // Store partial sums (fp16, no residual/gamma yet)
    #pragma unroll
    for (int ni = 0; ni < 4; ni++) {
        #pragma unroll
        for (int rh = 0; rh < 2; rh++) {
            int w = mi * 16 + gid + rh * 8;
            #pragma unroll
            for (int cp = 0; cp < 2; cp++) {
                int c = cBase + nq * 32 + ni * 8 + tig * 2 + cp;
                size_t idx = ((size_t)(b * NC + c) * NH + h) * NW + w;
                od[idx] = __float2half(acc[ni][rh * 2 + cp]);
            }
        }
    }
}

// ---------------------------------------------------------------------------
// aggH_f16 v7 (runs SECOND): R13 structure + final combine epilogue:
//   y = x + g * (accH + outW)
// 512 threads, 16 warps = wh(2) x mi(4) x nh(2). Smem 92KB.
// ---------------------------------------------------------------------------
#define AGH_AT_U32 (8 * 64 * 36)     // 18432
#define AGH_VS_U32 (8 * 16 * 36)     // 4608
#define AGH_SMEM   ((AGH_AT_U32 + AGH_VS_U32) * 4)   // 92160 B

__global__ void __launch_bounds__(512)
aggH_f16(const __half* __restrict__ v2, const __half* __restrict__ v1,
         const float* __restrict__ x2, const float* __restrict__ x1,
         const __half* __restrict__ atth, const __half* __restrict__ outw,
         const float* __restrict__ gamma, float* __restrict__ y)
{
    extern __shared__ uint32_t sm[];
    uint32_t* attS = sm;                    // [8][64][36]
    uint32_t* Vs   = sm + AGH_AT_U32;       // [8][16][36]

    const int t  = threadIdx.x;
    const int wg = blockIdx.x;              // 0..7
    const int cs = blockIdx.y;              // s*32 + cc
    const int b  = blockIdx.z;
    const int s  = cs >> 5;
    const int cBase = (cs & 31) * 16;
    const int w0 = wg * 8;

    const __half* v = s ? v1 : v2;
    const float*  x = s ? x1 : x2;
    const __half* ow = outw + (size_t)s * NB * NC * HWP;
    float* yd = y + (size_t)s * NB * NC * HWP;
    const float g = gamma[0];

    #pragma unroll
    for (int i = 0; i < 8; i++) {
        int f = t + i * 512;
        int w = f >> 9;
        int r = f & 511;
        int h = r >> 3, q8 = r & 7;
        cp_async16(attS + (size_t)w * 64 * 36 + h * 36 + q8 * 4,
                   atth + (((size_t)(b * NH + h) * NW) + (w0 + w)) * 128 + q8 * 8);
    }
    CP_COMMIT();

    {
        int p = t;
        int ci = p >> 5, j = p & 31;
        const __half* src = v + (((size_t)(b * NC + cBase + ci) * NH) + 2 * j) * NW + w0;
        uint4 ra = *reinterpret_cast<const uint4*>(src);
        uint4 rb = *reinterpret_cast<const uint4*>(src + NW);
        const __half* ha = reinterpret_cast<const __half*>(&ra);
        const __half* hb = reinterpret_cast<const __half*>(&rb);
        #pragma unroll
        for (int w = 0; w < 8; w++) {
            __half2 u = __halves2half2(ha[w], hb[w]);
            Vs[(size_t)w * 16 * 36 + ci * 36 + j] = *reinterpret_cast<uint32_t*>(&u);
        }
    }
    CP_WAIT0();
    __syncthreads();

    const int warp = t >> 5, lane = t & 31;
    const int gid = lane >> 2, tig = lane & 3;
    const int wh = warp >> 3;            // 0..1
    const int mi = (warp >> 1) & 3;      // h-tile
    const int nh = warp & 1;             // c8 half

    float acc[4][4];
    #pragma unroll
    for (int w = 0; w < 4; w++)
        #pragma unroll
        for (int r = 0; r < 4; r++) acc[w][r] = 0.f;

    #pragma unroll
    for (int w = 0; w < 4; w++) {
        const int wglob = wh * 4 + w;
        const uint32_t* Ac = attS + (size_t)wglob * 64 * 36;
        const uint32_t* Vw = Vs + (size_t)wglob * 16 * 36;
        #pragma unroll
        for (int k = 0; k < 4; k++) {
            const int kk2 = k * 8;
            const int m = mi * 16;
            uint32_t a0 = Ac[(m + gid    ) * 36 + kk2 + tig    ];
            uint32_t a1 = Ac[(m + gid + 8) * 36 + kk2 + tig    ];
            uint32_t a2 = Ac[(m + gid    ) * 36 + kk2 + tig + 4];
            uint32_t a3 = Ac[(m + gid + 8) * 36 + kk2 + tig + 4];
            int n = nh * 8 + gid;
            uint32_t b0 = Vw[n * 36 + kk2 + tig    ];
            uint32_t b1 = Vw[n * 36 + kk2 + tig + 4];
            mma_f16(acc[w][0], acc[w][1], acc[w][2], acc[w][3],
                    a0, a1, a2, a3, b0, b1);
        }
    }

    // Combine epilogue: y = x + g*(accH + outW)
    #pragma unroll
    for (int rh = 0; rh < 2; rh++) {
        #pragma unroll
        for (int cp = 0; cp < 2; cp++) {
            int h = mi * 16 + gid + rh * 8;
            int c = cBase + nh * 8 + tig * 2 + cp;
            size_t base = ((size_t)(b * NC + c) * NH + h) * NW + w0 + wh * 4;
            float4 xv = *reinterpret_cast<const float4*>(x + base);
            // 4 outW halves (8B)
            uint2 owp = *reinterpret_cast<const uint2*>(ow + base);
            __half2 o01 = *reinterpret_cast<__half2*>(&owp.x);
            __half2 o23 = *reinterpret_cast<__half2*>(&owp.y);
            float2 f01 = __half22float2(o01);
            float2 f23 = __half22float2(o23);
            float4 o;
            o.x = xv.x + g * (acc[0][rh * 2 + cp] + f01.x);
            o.y = xv.y + g * (acc[1][rh * 2 + cp] + f01.y);
            o.z = xv.z + g * (acc[2][rh * 2 + cp] + f23.x);
            o.w = xv.w + g * (acc[3][rh * 2 + cp] + f23.y);
            *reinterpret_cast<float4*>(yd + base) = o;
        }
    }
}

// ---------------------------------------------------------------------------
extern "C" void kernel_launch(void* const* d_in, const int* in_sizes, int n_in,
                              void* d_out, int out_size)
{
    const float* x2    = (const float*)d_in[0];
    const float* x1    = (const float*)d_in[1];
    const float* q_w   = (const float*)d_in[2];
    const float* q_b   = (const float*)d_in[3];
    const float* k_w   = (const float*)d_in[4];
    const float* k_b   = (const float*)d_in[5];
    const float* v_w   = (const float*)d_in[6];
    const float* v_b   = (const float*)d_in[7];
    const float* gamma = (const float*)d_in[8];
    float* y = (float*)d_out;

    float *gq, *gk, *gatt;
    __half *gv2, *gv1, *gatth, *goutw;
    cudaGetSymbolAddress((void**)&gq,    g_q);
    cudaGetSymbolAddress((void**)&gk,    g_k);
    cudaGetSymbolAddress((void**)&gv2,   g_v2h);
    cudaGetSymbolAddress((void**)&gv1,   g_v1h);
    cudaGetSymbolAddress((void**)&gatt,  g_att);
    cudaGetSymbolAddress((void**)&gatth, g_atth);
    cudaGetSymbolAddress((void**)&goutw, g_outw);

    cudaFuncSetAttribute(aggH_f16, cudaFuncAttributeMaxDynamicSharedMemorySize, AGH_SMEM);

    // Launch order: ncu capture slot = 4th launch = aggW_f16 (first profile).
    gemm_all<<<dim3(32, 4, 24), 256>>>(v_w, v_b, q_w, q_b, k_w, k_b,
                                       x2, x1, gv2, gv1, gq, gk);
    energy_HW<<<dim3(64, 2, NB), 256>>>(gq, gk, gatt);
    softmax_kernel<<<(NB * HWP) / 8, 256>>>(gatt, gatth);
    aggW_f16<<<dim3(NH, 8, NB), 512>>>(gv2, gv1, gatth, goutw);
    aggH_f16<<<dim3(8, 64, NB), 512, AGH_SMEM>>>(gv2, gv1, x2, x1, gatth, goutw, gamma, y);
}

// round 15
// speedup vs baseline: 1.0391x; 1.0391x over previous
#include <cuda_runtime.h>
#include <cuda_fp16.h>
#include <cstddef>
#include <cstdint>

// Problem constants
#define NB 8
#define NC 512
#define NH 64
#define NW 64
#define NCQ 64
#define HWP 4096   // NH*NW
#define KDIM 512

// Scratch (statically allocated device globals; no cudaMalloc allowed)
__device__ float  g_q  [NB * NCQ * HWP];
__device__ float  g_k  [NB * NCQ * HWP];
__device__ __half g_v2h[NB * NC  * HWP];        // 32 MB
__device__ __half g_v1h[NB * NC  * HWP];        // 32 MB
__device__ float  g_att [NB * HWP * 128];       // fp32 energies
__device__ __half g_atth[NB * HWP * 128];       // fp16 softmax output
__device__ __half g_outh[2 * NB * NC * HWP];    // 67 MB: aggH partial sums
__device__ __half g_outw[2 * NB * NC * HWP];    // 67 MB: aggW partial sums

__device__ __forceinline__ uint32_t pack_h2(float a, float b) {
    __half2 h = __floats2half2_rn(a, b);
    return *reinterpret_cast<uint32_t*>(&h);
}

__device__ __forceinline__ void mma_f16(float& d0, float& d1, float& d2, float& d3,
                                        uint32_t a0, uint32_t a1, uint32_t a2, uint32_t a3,
                                        uint32_t b0, uint32_t b1) {
    asm volatile(
        "mma.sync.aligned.m16n8k16.row.col.f32.f16.f16.f32 "
        "{%0,%1,%2,%3}, {%4,%5,%6,%7}, {%8,%9}, {%0,%1,%2,%3};"
        : "+f"(d0), "+f"(d1), "+f"(d2), "+f"(d3)
        : "r"(a0), "r"(a1), "r"(a2), "r"(a3), "r"(b0), "r"(b1));
}

__device__ __forceinline__ void cp_async16(void* smem_dst, const void* gsrc) {
    uint32_t d = (uint32_t)__cvta_generic_to_shared(smem_dst);
    asm volatile("cp.async.cg.shared.global [%0], [%1], 16;\n" :: "r"(d), "l"(gsrc));
}
#define CP_COMMIT() asm volatile("cp.async.commit_group;\n" ::: "memory")
#define CP_WAIT0()  asm volatile("cp.async.wait_group 0;\n" ::: "memory")

// ---------------------------------------------------------------------------
// gemm_all (unchanged): all projections, fp16 mma.
// ---------------------------------------------------------------------------
__global__ void __launch_bounds__(256)
gemm_all(const float* __restrict__ vw, const float* __restrict__ vb,
         const float* __restrict__ qw, const float* __restrict__ qb,
         const float* __restrict__ kw, const float* __restrict__ kb,
         const float* __restrict__ x2, const float* __restrict__ x1,
         __half* __restrict__ gv2, __half* __restrict__ gv1,
         float* __restrict__ gq,  float* __restrict__ gk)
{
    constexpr int NKT = KDIM / 32;

    __shared__ alignas(16) uint32_t As2[2][16][132];
    __shared__ alignas(16) uint32_t Bs2[2][16][136];

    const int t = threadIdx.x;
    const int z = blockIdx.z;
    const bool qkm = (z >= 16);
    if (qkm && blockIdx.y != 0) return;
    const int b = qkm ? (z - 16) : (z & 7);
    const int s = qkm ? 0 : (z >> 3);
    const int m0 = qkm ? 0 : blockIdx.y * 128;
    const int n0 = blockIdx.x * 128;

    const float* Xb = (qkm ? x2 : (s ? x1 : x2)) + (size_t)b * KDIM * HWP + n0;

    const int warp = t >> 5, lane = t & 31;
    const int gid = lane >> 2, tig = lane & 3;
    const int wm = warp >> 1, wn = warp & 1;

    float acc[2][8][4];
    #pragma unroll
    for (int mi = 0; mi < 2; mi++)
        #pragma unroll
        for (int ni = 0; ni < 8; ni++)
            #pragma unroll
            for (int r = 0; r < 4; r++) acc[mi][ni][r] = 0.f;

    float4 pb[2][2];
    float4 pa[4];

    auto loadA = [&](int kt) {
        #pragma unroll
        for (int i = 0; i < 4; i++) {
            int fa = t + i * 256;
            int row = fa >> 3, c4 = fa & 7;
            const float* src;
            if (qkm) {
                src = (row < 64) ? (qw + (size_t)row * KDIM)
                                 : (kw + (size_t)(row - 64) * KDIM);
            } else {
                src = vw + (size_t)(m0 + row) * KDIM;
            }
            pa[i] = *reinterpret_cast<const float4*>(src + kt * 32 + c4 * 4);
        }
    };
    auto storeA = [&](int buf) {
        #pragma unroll
        for (int i = 0; i < 4; i++) {
            int fa = t + i * 256;
            int row = fa >> 3, c4 = fa & 7;
            As2[buf][2 * c4    ][row] = pack_h2(pa[i].x, pa[i].y);
            As2[buf][2 * c4 + 1][row] = pack_h2(pa[i].z, pa[i].w);
        }
    };
    auto loadB = [&](int kt) {
        #pragma unroll
        for (int i = 0; i < 2; i++) {
            int fb = t + i * 256;
            int k2 = fb >> 5, n4 = fb & 31;
            const float* base = Xb + (size_t)(kt * 32 + 2 * k2) * HWP + n4 * 4;
            pb[i][0] = *reinterpret_cast<const float4*>(base);
            pb[i][1] = *reinterpret_cast<const float4*>(base + HWP);
        }
    };
    auto storeB = [&](int buf) {
        #pragma unroll
        for (int i = 0; i < 2; i++) {
            int fb = t + i * 256;
            int k2 = fb >> 5, n4 = fb & 31;
            uint4 u;
            u.x = pack_h2(pb[i][0].x, pb[i][1].x);
            u.y = pack_h2(pb[i][0].y, pb[i][1].y);
            u.z = pack_h2(pb[i][0].z, pb[i][1].z);
            u.w = pack_h2(pb[i][0].w, pb[i][1].w);
            *reinterpret_cast<uint4*>(&Bs2[buf][k2][n4 * 4]) = u;
        }
    };

    loadA(0); storeA(0);
    loadB(0); storeB(0);
    __syncthreads();

    for (int kt = 0; kt < NKT; kt++) {
        const int cur = kt & 1;
        if (kt + 1 < NKT) { loadA(kt + 1); loadB(kt + 1); }

        #pragma unroll
        for (int ks = 0; ks < 2; ks++) {
            const int kr = ks * 8;
            uint32_t af[2][4];
            #pragma unroll
            for (int mi = 0; mi < 2; mi++) {
                int m = wm * 32 + mi * 16;
                af[mi][0] = As2[cur][kr + tig    ][m + gid];
                af[mi][1] = As2[cur][kr + tig    ][m + gid + 8];
                af[mi][2] = As2[cur][kr + tig + 4][m + gid];
                af[mi][3] = As2[cur][kr + tig + 4][m + gid + 8];
            }
            #pragma unroll
            for (int ni = 0; ni < 8; ni++) {
                int n = wn * 64 + ni * 8 + gid;
                uint32_t b0 = Bs2[cur][kr + tig    ][n];
                uint32_t b1 = Bs2[cur][kr + tig + 4][n];
                #pragma unroll
                for (int mi = 0; mi < 2; mi++)
                    mma_f16(acc[mi][ni][0], acc[mi][ni][1], acc[mi][ni][2], acc[mi][ni][3],
                            af[mi][0], af[mi][1], af[mi][2], af[mi][3], b0, b1);
            }
        }

        if (kt + 1 < NKT) {
            __syncthreads();
            storeA(cur ^ 1); storeB(cur ^ 1);
            __syncthreads();
        }
    }

    #pragma unroll
    for (int mi = 0; mi < 2; mi++) {
        int ml = wm * 32 + mi * 16 + gid;
        #pragma unroll
        for (int half = 0; half < 2; half++) {
            int m = m0 + ml + half * 8;
            if (qkm) {
                float bv;
                float* obase;
                if (m < 64) { bv = qb[m];      obase = gq + ((size_t)b * 64 + m)        * HWP; }
                else        { bv = kb[m - 64]; obase = gk + ((size_t)b * 64 + (m - 64)) * HWP; }
                #pragma unroll
                for (int ni = 0; ni < 8; ni++) {
                    int n = n0 + wn * 64 + ni * 8 + tig * 2;
                    float2 o;
                    o.x = acc[mi][ni][half * 2 + 0] + bv;
                    o.y = acc[mi][ni][half * 2 + 1] + bv;
                    *reinterpret_cast<float2*>(obase + n) = o;
                }
            } else {
                float bv = vb[m];
                __half* O = s ? gv1 : gv2;
                __half* obase = O + ((size_t)b * NC + m) * HWP;
                #pragma unroll
                for (int ni = 0; ni < 8; ni++) {
                    int n = n0 + wn * 64 + ni * 8 + tig * 2;
                    *reinterpret_cast<uint32_t*>(obase + n) =
                        pack_h2(acc[mi][ni][half * 2 + 0] + bv,
                                acc[mi][ni][half * 2 + 1] + bv);
                }
            }
        }
    }
}

// ---------------------------------------------------------------------------
// energy_HW (unchanged)
// ---------------------------------------------------------------------------
__global__ void energy_HW(const float* __restrict__ q,
                          const float* __restrict__ k,
                          float* __restrict__ att)
{
    __shared__ float Qs[64][65];
    __shared__ float Ks[64][65];
    const int t = threadIdx.x;
    const int b = blockIdx.z;
    const int tx = t & 15, ty = t >> 4;

    if (blockIdx.y == 0) {
        const int w = blockIdx.x;
        #pragma unroll
        for (int i = 0; i < 16; i++) {
            int idx = t + i * 256;
            int c = idx >> 6, h = idx & 63;
            size_t g = ((size_t)(b * NCQ + c) * NH + h) * NW + w;
            Qs[c][h] = q[g];
            Ks[c][h] = k[g];
        }
        __syncthreads();
        float acc[4][4];
        #pragma unroll
        for (int i = 0; i < 4; i++)
            #pragma unroll
            for (int j = 0; j < 4; j++) acc[i][j] = 0.f;
        for (int c = 0; c < 64; c++) {
            float qa[4], kb[4];
            #pragma unroll
            for (int i = 0; i < 4; i++) qa[i] = Qs[c][ty * 4 + i];
            #pragma unroll
            for (int j = 0; j < 4; j++) kb[j] = Ks[c][tx * 4 + j];
            #pragma unroll
            for (int i = 0; i < 4; i++)
                #pragma unroll
                for (int j = 0; j < 4; j++) acc[i][j] += qa[i] * kb[j];
        }
        #pragma unroll
        for (int i = 0; i < 4; i++) {
            int h = ty * 4 + i;
            float4 o = {acc[i][0], acc[i][1], acc[i][2], acc[i][3]};
            *reinterpret_cast<float4*>(&att[((size_t)(b * NH + h) * NW + w) * 128 + tx * 4]) = o;
        }
    } else {
        const int h = blockIdx.x;
        #pragma unroll
        for (int i = 0; i < 16; i++) {
            int idx = t + i * 256;
            int c = idx >> 6, w = idx & 63;
            size_t g = ((size_t)(b * NCQ + c) * NH + h) * NW + w;
            Qs[c][w] = q[g];
            Ks[c][w] = k[g];
        }
        __syncthreads();
        float acc[4][4];
        #pragma unroll
        for (int i = 0; i < 4; i++)
            #pragma unroll
            for (int j = 0; j < 4; j++) acc[i][j] = 0.f;
        for (int c = 0; c < 64; c++) {
            float qa[4], kb[4];
            #pragma unroll
            for (int i = 0; i < 4; i++) qa[i] = Qs[c][ty * 4 + i];
            #pragma unroll
            for (int j = 0; j < 4; j++) kb[j] = Ks[c][tx * 4 + j];
            #pragma unroll
            for (int i = 0; i < 4; i++)
                #pragma unroll
                for (int j = 0; j < 4; j++) acc[i][j] += qa[i] * kb[j];
        }
        #pragma unroll
        for (int i = 0; i < 4; i++) {
            int w = ty * 4 + i;
            float4 o = {acc[i][0], acc[i][1], acc[i][2], acc[i][3]};
            *reinterpret_cast<float4*>(&att[((size_t)(b * NH + h) * NW + w) * 128 + 64 + tx * 4]) = o;
        }
    }
}

// ---------------------------------------------------------------------------
// softmax: fp32 in -> fp16 out (unchanged)
// ---------------------------------------------------------------------------
__global__ void softmax_kernel(const float* __restrict__ att,
                               __half* __restrict__ atth)
{
    int gwarp = (blockIdx.x * blockDim.x + threadIdx.x) >> 5;
    int lane  = threadIdx.x & 31;
    if (gwarp >= NB * HWP) return;
    const float4* row = reinterpret_cast<const float4*>(att) + (size_t)gwarp * 32;
    float4 v = row[lane];
    float m = fmaxf(fmaxf(v.x, v.y), fmaxf(v.z, v.w));
    #pragma unroll
    for (int o = 16; o > 0; o >>= 1) m = fmaxf(m, __shfl_xor_sync(0xFFFFFFFFu, m, o));
    v.x = __expf(v.x - m); v.y = __expf(v.y - m);
    v.z = __expf(v.z - m); v.w = __expf(v.w - m);
    float s = v.x + v.y + v.z + v.w;
    #pragma unroll
    for (int o = 16; o > 0; o >>= 1) s += __shfl_xor_sync(0xFFFFFFFFu, s, o);
    float r = 1.0f / s;
    uint2 o;
    o.x = pack_h2(v.x * r, v.y * r);
    o.y = pack_h2(v.z * r, v.w * r);
    *(reinterpret_cast<uint2*>(atth + (size_t)gwarp * 128) + lane) = o;
}

// ---------------------------------------------------------------------------
// aggH_f16 v8: writes fp16 partial sums outH (no x read, no y write).
// R13 structure: W8/C16 tiles, 512 threads, 16 warps = wh(2) x mi(4) x nh(2).
// ---------------------------------------------------------------------------
#define AGH_AT_U32 (8 * 64 * 36)     // 18432
#define AGH_VS_U32 (8 * 16 * 36)     // 4608
#define AGH_SMEM   ((AGH_AT_U32 + AGH_VS_U32) * 4)   // 92160 B

__global__ void __launch_bounds__(512)
aggH_f16(const __half* __restrict__ v2, const __half* __restrict__ v1,
         const __half* __restrict__ atth, __half* __restrict__ outh)
{
    extern __shared__ uint32_t sm[];
    uint32_t* attS = sm;                    // [8][64][36]
    uint32_t* Vs   = sm + AGH_AT_U32;       // [8][16][36]

    const int t  = threadIdx.x;
    const int wg = blockIdx.x;              // 0..7
    const int cs = blockIdx.y;              // s*32 + cc
    const int b  = blockIdx.z;
    const int s  = cs >> 5;
    const int cBase = (cs & 31) * 16;
    const int w0 = wg * 8;

    const __half* v = s ? v1 : v2;
    __half* od = outh + (size_t)s * NB * NC * HWP;

    #pragma unroll
    for (int i = 0; i < 8; i++) {
        int f = t + i * 512;
        int w = f >> 9;
        int r = f & 511;
        int h = r >> 3, q8 = r & 7;
        cp_async16(attS + (size_t)w * 64 * 36 + h * 36 + q8 * 4,
                   atth + (((size_t)(b * NH + h) * NW) + (w0 + w)) * 128 + q8 * 8);
    }
    CP_COMMIT();

    {
        int p = t;
        int ci = p >> 5, j = p & 31;
        const __half* src = v + (((size_t)(b * NC + cBase + ci) * NH) + 2 * j) * NW + w0;
        uint4 ra = *reinterpret_cast<const uint4*>(src);
        uint4 rb = *reinterpret_cast<const uint4*>(src + NW);
        const __half* ha = reinterpret_cast<const __half*>(&ra);
        const __half* hb = reinterpret_cast<const __half*>(&rb);
        #pragma unroll
        for (int w = 0; w < 8; w++) {
            __half2 u = __halves2half2(ha[w], hb[w]);
            Vs[(size_t)w * 16 * 36 + ci * 36 + j] = *reinterpret_cast<uint32_t*>(&u);
        }
    }
    CP_WAIT0();
    __syncthreads();

    const int warp = t >> 5, lane = t & 31;
    const int gid = lane >> 2, tig = lane & 3;
    const int wh = warp >> 3;            // 0..1
    const int mi = (warp >> 1) & 3;      // h-tile
    const int nh = warp & 1;             // c8 half

    float acc[4][4];
    #pragma unroll
    for (int w = 0; w < 4; w++)
        #pragma unroll
        for (int r = 0; r < 4; r++) acc[w][r] = 0.f;

    #pragma unroll
    for (int w = 0; w < 4; w++) {
        const int wglob = wh * 4 + w;
        const uint32_t* Ac = attS + (size_t)wglob * 64 * 36;
        const uint32_t* Vw = Vs + (size_t)wglob * 16 * 36;
        #pragma unroll
        for (int k = 0; k < 4; k++) {
            const int kk2 = k * 8;
            const int m = mi * 16;
            uint32_t a0 = Ac[(m + gid    ) * 36 + kk2 + tig    ];
            uint32_t a1 = Ac[(m + gid + 8) * 36 + kk2 + tig    ];
            uint32_t a2 = Ac[(m + gid    ) * 36 + kk2 + tig + 4];
            uint32_t a3 = Ac[(m + gid + 8) * 36 + kk2 + tig + 4];
            int n = nh * 8 + gid;
            uint32_t b0 = Vw[n * 36 + kk2 + tig    ];
            uint32_t b1 = Vw[n * 36 + kk2 + tig + 4];
            mma_f16(acc[w][0], acc[w][1], acc[w][2], acc[w][3],
                    a0, a1, a2, a3, b0, b1);
        }
    }

    // Epilogue: outH[c][h][w0+wh*4 .. +3] = acc (one uint2 = 4 halves per (h,c))
    #pragma unroll
    for (int rh = 0; rh < 2; rh++) {
        #pragma unroll
        for (int cp = 0; cp < 2; cp++) {
            int h = mi * 16 + gid + rh * 8;
            int c = cBase + nh * 8 + tig * 2 + cp;
            size_t base = ((size_t)(b * NC + c) * NH + h) * NW + w0 + wh * 4;
            uint2 o;
            o.x = pack_h2(acc[0][rh * 2 + cp], acc[1][rh * 2 + cp]);
            o.y = pack_h2(acc[2][rh * 2 + cp], acc[3][rh * 2 + cp]);
            *reinterpret_cast<uint2*>(od + base) = o;
        }
    }
}

// ---------------------------------------------------------------------------
// aggW_f16 (R14, measured 40us): writes fp16 partial sums outW.
// ---------------------------------------------------------------------------
__global__ void __launch_bounds__(512)
aggW_f16(const __half* __restrict__ v2, const __half* __restrict__ v1,
         const __half* __restrict__ atth, __half* __restrict__ outw)
{
    __shared__ alignas(16) uint32_t Ast[64 * 36];
    __shared__ alignas(16) uint32_t Vst[128 * 36];

    const int t  = threadIdx.x;
    const int h  = blockIdx.x;
    const int cs = blockIdx.y;         // s*4 + cc
    const int b  = blockIdx.z;
    const int s  = cs >> 2;
    const int cBase = (cs & 3) * 128;

    const __half* v = s ? v1 : v2;
    __half* od = outw + (size_t)s * NB * NC * HWP;

    {
        int f = t;
        int r = f >> 3, q8 = f & 7;
        cp_async16(Ast + r * 36 + q8 * 4,
                   atth + (((size_t)(b * NH + h) * NW) + r) * 128 + 64 + q8 * 8);
    }
    #pragma unroll
    for (int i = 0; i < 2; i++) {
        int f = t + i * 512;
        int r = f >> 3, q8 = f & 7;
        cp_async16(Vst + r * 36 + q8 * 4,
                   v + (((size_t)(b * NC + cBase + r) * NH) + h) * NW + q8 * 8);
    }
    CP_COMMIT();
    CP_WAIT0();
    __syncthreads();

    const int warp = t >> 5, lane = t & 31;
    const int gid = lane >> 2, tig = lane & 3;
    const int mi = warp >> 2;      // w-tile (m16)
    const int nq = warp & 3;       // c32 quarter

    float acc[4][4];
    #pragma unroll
    for (int ni = 0; ni < 4; ni++)
        #pragma unroll
        for (int r = 0; r < 4; r++) acc[ni][r] = 0.f;

    #pragma unroll
    for (int k = 0; k < 4; k++) {
        const int kk2 = k * 8;
        const int m = mi * 16;
        uint32_t a0 = Ast[(m + gid    ) * 36 + kk2 + tig    ];
        uint32_t a1 = Ast[(m + gid + 8) * 36 + kk2 + tig    ];
        uint32_t a2 = Ast[(m + gid    ) * 36 + kk2 + tig + 4];
        uint32_t a3 = Ast[(m + gid + 8) * 36 + kk2 + tig + 4];
        #pragma unroll
        for (int ni = 0; ni < 4; ni++) {
            int n = nq * 32 + ni * 8 + gid;
            uint32_t b0 = Vst[n * 36 + kk2 + tig    ];
            uint32_t b1 = Vst[n * 36 + kk2 + tig + 4];
            mma_f16(acc[ni][0], acc[ni][1], acc[ni][2], acc[ni][3],
                    a0, a1, a2, a3, b0, b1);
        }
    }

    #pragma unroll
    for (int ni = 0; ni < 4; ni++) {
        #pragma unroll
        for (int rh = 0; rh < 2; rh++) {
            int w = mi * 16 + gid + rh * 8;
            #pragma unroll
            for (int cp = 0; cp < 2; cp++) {
                int c = cBase + nq * 32 + ni * 8 + tig * 2 + cp;
                size_t idx = ((size_t)(b * NC + c) * NH + h) * NW + w;
                od[idx] = __float2half(acc[ni][rh * 2 + cp]);
            }
        }
    }
}

// ---------------------------------------------------------------------------
// combine: y = x + g*(outH + outW).  Perfectly coalesced streaming kernel.
// Thread handles 8 consecutive elements. Grid (4096, 2).
// ---------------------------------------------------------------------------
__global__ void __launch_bounds__(512)
combine_kernel(const float* __restrict__ x2, const float* __restrict__ x1,
               const __half* __restrict__ outh, const __half* __restrict__ outw,
               const float* __restrict__ gamma, float* __restrict__ y)
{
    const size_t N = (size_t)NB * NC * HWP;
    const int sIdx = blockIdx.y;
    const float* x = sIdx ? x1 : x2;
    const __half* oh = outh + sIdx * N;
    const __half* ow = outw + sIdx * N;
    float* yd = y + sIdx * N;
    const float g = gamma[0];

    size_t i = ((size_t)blockIdx.x * 512 + threadIdx.x) * 8;

    float4 xa = *reinterpret_cast<const float4*>(x + i);
    float4 xb = *reinterpret_cast<const float4*>(x + i + 4);
    uint4 hu = *reinterpret_cast<const uint4*>(oh + i);   // 8 halves
    uint4 wu = *reinterpret_cast<const uint4*>(ow + i);

    float2 h0 = __half22float2(*reinterpret_cast<__half2*>(&hu.x));
    float2 h1 = __half22float2(*reinterpret_cast<__half2*>(&hu.y));
    float2 h2 = __half22float2(*reinterpret_cast<__half2*>(&hu.z));
    float2 h3 = __half22float2(*reinterpret_cast<__half2*>(&hu.w));
    float2 w0 = __half22float2(*reinterpret_cast<__half2*>(&wu.x));
    float2 w1 = __half22float2(*reinterpret_cast<__half2*>(&wu.y));
    float2 w2 = __half22float2(*reinterpret_cast<__half2*>(&wu.z));
    float2 w3 = __half22float2(*reinterpret_cast<__half2*>(&wu.w));

    float4 oa, ob;
    oa.x = xa.x + g * (h0.x + w0.x);
    oa.y = xa.y + g * (h0.y + w0.y);
    oa.z = xa.z + g * (h1.x + w1.x);
    oa.w = xa.w + g * (h1.y + w1.y);
    ob.x = xb.x + g * (h2.x + w2.x);
    ob.y = xb.y + g * (h2.y + w2.y);
    ob.z = xb.z + g * (h3.x + w3.x);
    ob.w = xb.w + g * (h3.y + w3.y);

    *reinterpret_cast<float4*>(yd + i)     = oa;
    *reinterpret_cast<float4*>(yd + i + 4) = ob;
}

// ---------------------------------------------------------------------------
extern "C" void kernel_launch(void* const* d_in, const int* in_sizes, int n_in,
                              void* d_out, int out_size)
{
    const float* x2    = (const float*)d_in[0];
    const float* x1    = (const float*)d_in[1];
    const float* q_w   = (const float*)d_in[2];
    const float* q_b   = (const float*)d_in[3];
    const float* k_w   = (const float*)d_in[4];
    const float* k_b   = (const float*)d_in[5];
    const float* v_w   = (const float*)d_in[6];
    const float* v_b   = (const float*)d_in[7];
    const float* gamma = (const float*)d_in[8];
    float* y = (float*)d_out;

    float *gq, *gk, *gatt;
    __half *gv2, *gv1, *gatth, *gouth, *goutw;
    cudaGetSymbolAddress((void**)&gq,    g_q);
    cudaGetSymbolAddress((void**)&gk,    g_k);
    cudaGetSymbolAddress((void**)&gv2,   g_v2h);
    cudaGetSymbolAddress((void**)&gv1,   g_v1h);
    cudaGetSymbolAddress((void**)&gatt,  g_att);
    cudaGetSymbolAddress((void**)&gatth, g_atth);
    cudaGetSymbolAddress((void**)&gouth, g_outh);
    cudaGetSymbolAddress((void**)&goutw, g_outw);

    cudaFuncSetAttribute(aggH_f16, cudaFuncAttributeMaxDynamicSharedMemorySize, AGH_SMEM);

    // Launch order: ncu capture slot = 4th launch = aggH_f16 (v8 profile).
    gemm_all<<<dim3(32, 4, 24), 256>>>(v_w, v_b, q_w, q_b, k_w, k_b,
                                       x2, x1, gv2, gv1, gq, gk);
    energy_HW<<<dim3(64, 2, NB), 256>>>(gq, gk, gatt);
    softmax_kernel<<<(NB * HWP) / 8, 256>>>(gatt, gatth);
    aggH_f16<<<dim3(8, 64, NB), 512, AGH_SMEM>>>(gv2, gv1, gatth, gouth);
    aggW_f16<<<dim3(NH, 8, NB), 512>>>(gv2, gv1, gatth, goutw);
    combine_kernel<<<dim3(4096, 2), 512>>>(x2, x1, gouth, goutw, gamma, y);
}

// round 16
// speedup vs baseline: 1.2125x; 1.1669x over previous
#include <cuda_runtime.h>
#include <cuda_fp16.h>
#include <cstddef>
#include <cstdint>

// Problem constants
#define NB 8
#define NC 512
#define NH 64
#define NW 64
#define NCQ 64
#define HWP 4096   // NH*NW
#define KDIM 512

// Scratch (statically allocated device globals; no cudaMalloc allowed)
__device__ float  g_q  [NB * NCQ * HWP];
__device__ float  g_k  [NB * NCQ * HWP];
__device__ __half g_v2h[NB * NC  * HWP];        // 32 MB
__device__ __half g_v1h[NB * NC  * HWP];        // 32 MB
__device__ float  g_att [NB * HWP * 128];       // fp32 energies
__device__ __half g_atth[NB * HWP * 128];       // fp16 softmax output
__device__ __half g_outh[2 * NB * NC * HWP];    // 67 MB: aggH partial sums
__device__ __half g_outw[2 * NB * NC * HWP];    // 67 MB: aggW partial sums
__device__ uint32_t g_whv [256 * 512];          // v_w as half2 pairs, [k2][m]
__device__ uint32_t g_whqk[256 * 128];          // q(0:64)+k(64:128) half2, [k2][m]

__device__ __forceinline__ uint32_t pack_h2(float a, float b) {
    __half2 h = __floats2half2_rn(a, b);
    return *reinterpret_cast<uint32_t*>(&h);
}

__device__ __forceinline__ void mma_f16(float& d0, float& d1, float& d2, float& d3,
                                        uint32_t a0, uint32_t a1, uint32_t a2, uint32_t a3,
                                        uint32_t b0, uint32_t b1) {
    asm volatile(
        "mma.sync.aligned.m16n8k16.row.col.f32.f16.f16.f32 "
        "{%0,%1,%2,%3}, {%4,%5,%6,%7}, {%8,%9}, {%0,%1,%2,%3};"
        : "+f"(d0), "+f"(d1), "+f"(d2), "+f"(d3)
        : "r"(a0), "r"(a1), "r"(a2), "r"(a3), "r"(b0), "r"(b1));
}

__device__ __forceinline__ void cp_async16(void* smem_dst, const void* gsrc) {
    uint32_t d = (uint32_t)__cvta_generic_to_shared(smem_dst);
    asm volatile("cp.async.cg.shared.global [%0], [%1], 16;\n" :: "r"(d), "l"(gsrc));
}
#define CP_COMMIT() asm volatile("cp.async.commit_group;\n" ::: "memory")
#define CP_WAIT0()  asm volatile("cp.async.wait_group 0;\n" ::: "memory")

// ---------------------------------------------------------------------------
// preconv: pack weights to half2 [k2][m] layout (one-time).
// ---------------------------------------------------------------------------
__global__ void preconv(const float* __restrict__ vw,
                        const float* __restrict__ qw,
                        const float* __restrict__ kw)
{
    int idx = blockIdx.x * 256 + threadIdx.x;
    if (idx < 512 * 256) {
        int m = idx >> 8, k2 = idx & 255;
        g_whv[k2 * 512 + m] = pack_h2(vw[(size_t)m * KDIM + 2 * k2],
                                      vw[(size_t)m * KDIM + 2 * k2 + 1]);
    } else {
        int r = idx - 512 * 256;
        int m = r >> 8, k2 = r & 255;
        const float* src = (m < 64) ? (qw + (size_t)m * KDIM)
                                    : (kw + (size_t)(m - 64) * KDIM);
        g_whqk[k2 * 128 + m] = pack_h2(src[2 * k2], src[2 * k2 + 1]);
    }
}

// ---------------------------------------------------------------------------
// gemm_v: v projections, BM=256 x BN=128 per block, 512 threads (8m x 2n
// warps), A from pre-packed fp16 weights via cp.async. X read once per 2
// m-tiles (halved vs R15). Output fp16.
// Grid (32, 2, 16): n-tile, m-half, z = s*8+b.
// ---------------------------------------------------------------------------
__global__ void __launch_bounds__(512)
gemm_v(const float* __restrict__ vb,
       const float* __restrict__ x2, const float* __restrict__ x1,
       __half* __restrict__ gv2, __half* __restrict__ gv1)
{
    constexpr int NKT = KDIM / 32;

    __shared__ alignas(16) uint32_t As2[2][16][260];   // [k2][m] halves-pairs
    __shared__ alignas(16) uint32_t Bs2[2][16][136];

    const int t = threadIdx.x;
    const int z = blockIdx.z;
    const int b = z & 7, s = z >> 3;
    const int m0 = blockIdx.y * 256;
    const int n0 = blockIdx.x * 128;

    const float* Xb = (s ? x1 : x2) + (size_t)b * KDIM * HWP + n0;

    const int warp = t >> 5, lane = t & 31;
    const int gid = lane >> 2, tig = lane & 3;
    const int wm = warp >> 1, wn = warp & 1;   // wm 0..7, wn 0..1

    float acc[2][8][4];
    #pragma unroll
    for (int mi = 0; mi < 2; mi++)
        #pragma unroll
        for (int ni = 0; ni < 8; ni++)
            #pragma unroll
            for (int r = 0; r < 4; r++) acc[mi][ni][r] = 0.f;

    float4 pb0, pb1;

    auto issueA = [&](int kt, int buf) {
        #pragma unroll
        for (int i = 0; i < 2; i++) {
            int f = t + i * 512;            // 0..1023
            int k2r = f >> 6, c4 = f & 63;  // 64 chunks of 4 u32 per k2-row
            cp_async16(&As2[buf][k2r][c4 * 4],
                       g_whv + (size_t)(kt * 16 + k2r) * 512 + m0 + c4 * 4);
        }
    };
    auto loadB = [&](int kt) {
        int k2 = t >> 5, n4 = t & 31;
        const float* base = Xb + (size_t)(kt * 32 + 2 * k2) * HWP + n4 * 4;
        pb0 = *reinterpret_cast<const float4*>(base);
        pb1 = *reinterpret_cast<const float4*>(base + HWP);
    };
    auto storeB = [&](int buf) {
        int k2 = t >> 5, n4 = t & 31;
        uint4 u;
        u.x = pack_h2(pb0.x, pb1.x);
        u.y = pack_h2(pb0.y, pb1.y);
        u.z = pack_h2(pb0.z, pb1.z);
        u.w = pack_h2(pb0.w, pb1.w);
        *reinterpret_cast<uint4*>(&Bs2[buf][k2][n4 * 4]) = u;
    };

    issueA(0, 0); CP_COMMIT();
    loadB(0); storeB(0);
    CP_WAIT0();
    __syncthreads();

    for (int kt = 0; kt < NKT; kt++) {
        const int cur = kt & 1;
        if (kt + 1 < NKT) { issueA(kt + 1, cur ^ 1); CP_COMMIT(); loadB(kt + 1); }

        #pragma unroll
        for (int ks = 0; ks < 2; ks++) {
            const int kr = ks * 8;
            uint32_t af[2][4];
            #pragma unroll
            for (int mi = 0; mi < 2; mi++) {
                int m = wm * 32 + mi * 16;
                af[mi][0] = As2[cur][kr + tig    ][m + gid];
                af[mi][1] = As2[cur][kr + tig    ][m + gid + 8];
                af[mi][2] = As2[cur][kr + tig + 4][m + gid];
                af[mi][3] = As2[cur][kr + tig + 4][m + gid + 8];
            }
            #pragma unroll
            for (int ni = 0; ni < 8; ni++) {
                int n = wn * 64 + ni * 8 + gid;
                uint32_t b0 = Bs2[cur][kr + tig    ][n];
                uint32_t b1 = Bs2[cur][kr + tig + 4][n];
                #pragma unroll
                for (int mi = 0; mi < 2; mi++)
                    mma_f16(acc[mi][ni][0], acc[mi][ni][1], acc[mi][ni][2], acc[mi][ni][3],
                            af[mi][0], af[mi][1], af[mi][2], af[mi][3], b0, b1);
            }
        }

        if (kt + 1 < NKT) {
            __syncthreads();
            storeB(cur ^ 1);
            CP_WAIT0();
            __syncthreads();
        }
    }

    __half* O = s ? gv1 : gv2;
    #pragma unroll
    for (int mi = 0; mi < 2; mi++) {
        int ml = wm * 32 + mi * 16 + gid;
        #pragma unroll
        for (int half = 0; half < 2; half++) {
            int m = m0 + ml + half * 8;
            float bv = vb[m];
            __half* obase = O + ((size_t)b * NC + m) * HWP;
            #pragma unroll
            for (int ni = 0; ni < 8; ni++) {
                int n = n0 + wn * 64 + ni * 8 + tig * 2;
                *reinterpret_cast<uint32_t*>(obase + n) =
                    pack_h2(acc[mi][ni][half * 2 + 0] + bv,
                            acc[mi][ni][half * 2 + 1] + bv);
            }
        }
    }
}

// ---------------------------------------------------------------------------
// gemm_qk: fused q+k (M=128), fp16 mma, A from pre-packed g_whqk.
// 256 threads, grid (32, 1, 8).
// ---------------------------------------------------------------------------
__global__ void __launch_bounds__(256)
gemm_qk(const float* __restrict__ qb, const float* __restrict__ kb,
        const float* __restrict__ x2,
        float* __restrict__ gq, float* __restrict__ gk)
{
    constexpr int NKT = KDIM / 32;

    __shared__ alignas(16) uint32_t As2[2][16][132];
    __shared__ alignas(16) uint32_t Bs2[2][16][136];

    const int t = threadIdx.x;
    const int b = blockIdx.z;
    const int n0 = blockIdx.x * 128;
    const float* Xb = x2 + (size_t)b * KDIM * HWP + n0;

    const int warp = t >> 5, lane = t & 31;
    const int gid = lane >> 2, tig = lane & 3;
    const int wm = warp >> 1, wn = warp & 1;

    float acc[2][8][4];
    #pragma unroll
    for (int mi = 0; mi < 2; mi++)
        #pragma unroll
        for (int ni = 0; ni < 8; ni++)
            #pragma unroll
            for (int r = 0; r < 4; r++) acc[mi][ni][r] = 0.f;

    float4 pb[2][2];

    auto issueA = [&](int kt, int buf) {
        #pragma unroll
        for (int i = 0; i < 2; i++) {
            int f = t + i * 256;            // 0..511
            int k2r = f >> 5, c4 = f & 31;  // 32 chunks per k2-row (128 m)
            cp_async16(&As2[buf][k2r][c4 * 4],
                       g_whqk + (size_t)(kt * 16 + k2r) * 128 + c4 * 4);
        }
    };
    auto loadB = [&](int kt) {
        #pragma unroll
        for (int i = 0; i < 2; i++) {
            int fb = t + i * 256;
            int k2 = fb >> 5, n4 = fb & 31;
            const float* base = Xb + (size_t)(kt * 32 + 2 * k2) * HWP + n4 * 4;
            pb[i][0] = *reinterpret_cast<const float4*>(base);
            pb[i][1] = *reinterpret_cast<const float4*>(base + HWP);
        }
    };
    auto storeB = [&](int buf) {
        #pragma unroll
        for (int i = 0; i < 2; i++) {
            int fb = t + i * 256;
            int k2 = fb >> 5, n4 = fb & 31;
            uint4 u;
            u.x = pack_h2(pb[i][0].x, pb[i][1].x);
            u.y = pack_h2(pb[i][0].y, pb[i][1].y);
            u.z = pack_h2(pb[i][0].z, pb[i][1].z);
            u.w = pack_h2(pb[i][0].w, pb[i][1].w);
            *reinterpret_cast<uint4*>(&Bs2[buf][k2][n4 * 4]) = u;
        }
    };

    issueA(0, 0); CP_COMMIT();
    loadB(0); storeB(0);
    CP_WAIT0();
    __syncthreads();

    for (int kt = 0; kt < NKT; kt++) {
        const int cur = kt & 1;
        if (kt + 1 < NKT) { issueA(kt + 1, cur ^ 1); CP_COMMIT(); loadB(kt + 1); }

        #pragma unroll
        for (int ks = 0; ks < 2; ks++) {
            const int kr = ks * 8;
            uint32_t af[2][4];
            #pragma unroll
            for (int mi = 0; mi < 2; mi++) {
                int m = wm * 32 + mi * 16;
                af[mi][0] = As2[cur][kr + tig    ][m + gid];
                af[mi][1] = As2[cur][kr + tig    ][m + gid + 8];
                af[mi][2] = As2[cur][kr + tig + 4][m + gid];
                af[mi][3] = As2[cur][kr + tig + 4][m + gid + 8];
            }
            #pragma unroll
            for (int ni = 0; ni < 8; ni++) {
                int n = wn * 64 + ni * 8 + gid;
                uint32_t b0 = Bs2[cur][kr + tig    ][n];
                uint32_t b1 = Bs2[cur][kr + tig + 4][n];
                #pragma unroll
                for (int mi = 0; mi < 2; mi++)
                    mma_f16(acc[mi][ni][0], acc[mi][ni][1], acc[mi][ni][2], acc[mi][ni][3],
                            af[mi][0], af[mi][1], af[mi][2], af[mi][3], b0, b1);
            }
        }

        if (kt + 1 < NKT) {
            __syncthreads();
            storeB(cur ^ 1);
            CP_WAIT0();
            __syncthreads();
        }
    }

    #pragma unroll
    for (int mi = 0; mi < 2; mi++) {
        int ml = wm * 32 + mi * 16 + gid;
        #pragma unroll
        for (int half = 0; half < 2; half++) {
            int m = ml + half * 8;
            float bv;
            float* obase;
            if (m < 64) { bv = qb[m];      obase = gq + ((size_t)b * 64 + m)        * HWP; }
            else        { bv = kb[m - 64]; obase = gk + ((size_t)b * 64 + (m - 64)) * HWP; }
            #pragma unroll
            for (int ni = 0; ni < 8; ni++) {
                int n = n0 + wn * 64 + ni * 8 + tig * 2;
                float2 o;
                o.x = acc[mi][ni][half * 2 + 0] + bv;
                o.y = acc[mi][ni][half * 2 + 1] + bv;
                *reinterpret_cast<float2*>(obase + n) = o;
            }
        }
    }
}

// ---------------------------------------------------------------------------
// energy_HW (unchanged)
// ---------------------------------------------------------------------------
__global__ void energy_HW(const float* __restrict__ q,
                          const float* __restrict__ k,
                          float* __restrict__ att)
{
    __shared__ float Qs[64][65];
    __shared__ float Ks[64][65];
    const int t = threadIdx.x;
    const int b = blockIdx.z;
    const int tx = t & 15, ty = t >> 4;

    if (blockIdx.y == 0) {
        const int w = blockIdx.x;
        #pragma unroll
        for (int i = 0; i < 16; i++) {
            int idx = t + i * 256;
            int c = idx >> 6, h = idx & 63;
            size_t g = ((size_t)(b * NCQ + c) * NH + h) * NW + w;
            Qs[c][h] = q[g];
            Ks[c][h] = k[g];
        }
        __syncthreads();
        float acc[4][4];
        #pragma unroll
        for (int i = 0; i < 4; i++)
            #pragma unroll
            for (int j = 0; j < 4; j++) acc[i][j] = 0.f;
        for (int c = 0; c < 64; c++) {
            float qa[4], kb[4];
            #pragma unroll
            for (int i = 0; i < 4; i++) qa[i] = Qs[c][ty * 4 + i];
            #pragma unroll
            for (int j = 0; j < 4; j++) kb[j] = Ks[c][tx * 4 + j];
            #pragma unroll
            for (int i = 0; i < 4; i++)
                #pragma unroll
                for (int j = 0; j < 4; j++) acc[i][j] += qa[i] * kb[j];
        }
        #pragma unroll
        for (int i = 0; i < 4; i++) {
            int h = ty * 4 + i;
            float4 o = {acc[i][0], acc[i][1], acc[i][2], acc[i][3]};
            *reinterpret_cast<float4*>(&att[((size_t)(b * NH + h) * NW + w) * 128 + tx * 4]) = o;
        }
    } else {
        const int h = blockIdx.x;
        #pragma unroll
        for (int i = 0; i < 16; i++) {
            int idx = t + i * 256;
            int c = idx >> 6, w = idx & 63;
            size_t g = ((size_t)(b * NCQ + c) * NH + h) * NW + w;
            Qs[c][w] = q[g];
            Ks[c][w] = k[g];
        }
        __syncthreads();
        float acc[4][4];
        #pragma unroll
        for (int i = 0; i < 4; i++)
            #pragma unroll
            for (int j = 0; j < 4; j++) acc[i][j] = 0.f;
        for (int c = 0; c < 64; c++) {
            float qa[4], kb[4];
            #pragma unroll
            for (int i = 0; i < 4; i++) qa[i] = Qs[c][ty * 4 + i];
            #pragma unroll
            for (int j = 0; j < 4; j++) kb[j] = Ks[c][tx * 4 + j];
            #pragma unroll
            for (int i = 0; i < 4; i++)
                #pragma unroll
                for (int j = 0; j < 4; j++) acc[i][j] += qa[i] * kb[j];
        }
        #pragma unroll
        for (int i = 0; i < 4; i++) {
            int w = ty * 4 + i;
            float4 o = {acc[i][0], acc[i][1], acc[i][2], acc[i][3]};
            *reinterpret_cast<float4*>(&att[((size_t)(b * NH + h) * NW + w) * 128 + 64 + tx * 4]) = o;
        }
    }
}

// ---------------------------------------------------------------------------
// softmax: fp32 in -> fp16 out (unchanged)
// ---------------------------------------------------------------------------
__global__ void softmax_kernel(const float* __restrict__ att,
                               __half* __restrict__ atth)
{
    int gwarp = (blockIdx.x * blockDim.x + threadIdx.x) >> 5;
    int lane  = threadIdx.x & 31;
    if (gwarp >= NB * HWP) return;
    const float4* row = reinterpret_cast<const float4*>(att) + (size_t)gwarp * 32;
    float4 v = row[lane];
    float m = fmaxf(fmaxf(v.x, v.y), fmaxf(v.z, v.w));
    #pragma unroll
    for (int o = 16; o > 0; o >>= 1) m = fmaxf(m, __shfl_xor_sync(0xFFFFFFFFu, m, o));
    v.x = __expf(v.x - m); v.y = __expf(v.y - m);
    v.z = __expf(v.z - m); v.w = __expf(v.w - m);
    float s = v.x + v.y + v.z + v.w;
    #pragma unroll
    for (int o = 16; o > 0; o >>= 1) s += __shfl_xor_sync(0xFFFFFFFFu, s, o);
    float r = 1.0f / s;
    uint2 o;
    o.x = pack_h2(v.x * r, v.y * r);
    o.y = pack_h2(v.z * r, v.w * r);
    *(reinterpret_cast<uint2*>(atth + (size_t)gwarp * 128) + lane) = o;
}

// ---------------------------------------------------------------------------
// aggH_f16 v8 (R15, measured 114us): fp16 partials -> outH.
// ---------------------------------------------------------------------------
#define AGH_AT_U32 (8 * 64 * 36)
#define AGH_VS_U32 (8 * 16 * 36)
#define AGH_SMEM   ((AGH_AT_U32 + AGH_VS_U32) * 4)

__global__ void __launch_bounds__(512)
aggH_f16(const __half* __restrict__ v2, const __half* __restrict__ v1,
         const __half* __restrict__ atth, __half* __restrict__ outh)
{
    extern __shared__ uint32_t sm[];
    uint32_t* attS = sm;
    uint32_t* Vs   = sm + AGH_AT_U32;

    const int t  = threadIdx.x;
    const int wg = blockIdx.x;
    const int cs = blockIdx.y;
    const int b  = blockIdx.z;
    const int s  = cs >> 5;
    const int cBase = (cs & 31) * 16;
    const int w0 = wg * 8;

    const __half* v = s ? v1 : v2;
    __half* od = outh + (size_t)s * NB * NC * HWP;

    #pragma unroll
    for (int i = 0; i < 8; i++) {
        int f = t + i * 512;
        int w = f >> 9;
        int r = f & 511;
        int h = r >> 3, q8 = r & 7;
        cp_async16(attS + (size_t)w * 64 * 36 + h * 36 + q8 * 4,
                   atth + (((size_t)(b * NH + h) * NW) + (w0 + w)) * 128 + q8 * 8);
    }
    CP_COMMIT();

    {
        int p = t;
        int ci = p >> 5, j = p & 31;
        const __half* src = v + (((size_t)(b * NC + cBase + ci) * NH) + 2 * j) * NW + w0;
        uint4 ra = *reinterpret_cast<const uint4*>(src);
        uint4 rb = *reinterpret_cast<const uint4*>(src + NW);
        const __half* ha = reinterpret_cast<const __half*>(&ra);
        const __half* hb = reinterpret_cast<const __half*>(&rb);
        #pragma unroll
        for (int w = 0; w < 8; w++) {
            __half2 u = __halves2half2(ha[w], hb[w]);
            Vs[(size_t)w * 16 * 36 + ci * 36 + j] = *reinterpret_cast<uint32_t*>(&u);
        }
    }
    CP_WAIT0();
    __syncthreads();

    const int warp = t >> 5, lane = t & 31;
    const int gid = lane >> 2, tig = lane & 3;
    const int wh = warp >> 3;
    const int mi = (warp >> 1) & 3;
    const int nh = warp & 1;

    float acc[4][4];
    #pragma unroll
    for (int w = 0; w < 4; w++)
        #pragma unroll
        for (int r = 0; r < 4; r++) acc[w][r] = 0.f;

    #pragma unroll
    for (int w = 0; w < 4; w++) {
        const int wglob = wh * 4 + w;
        const uint32_t* Ac = attS + (size_t)wglob * 64 * 36;
        const uint32_t* Vw = Vs + (size_t)wglob * 16 * 36;
        #pragma unroll
        for (int k = 0; k < 4; k++) {
            const int kk2 = k * 8;
            const int m = mi * 16;
            uint32_t a0 = Ac[(m + gid    ) * 36 + kk2 + tig    ];
            uint32_t a1 = Ac[(m + gid + 8) * 36 + kk2 + tig    ];
            uint32_t a2 = Ac[(m + gid    ) * 36 + kk2 + tig + 4];
            uint32_t a3 = Ac[(m + gid + 8) * 36 + kk2 + tig + 4];
            int n = nh * 8 + gid;
            uint32_t b0 = Vw[n * 36 + kk2 + tig    ];
            uint32_t b1 = Vw[n * 36 + kk2 + tig + 4];
            mma_f16(acc[w][0], acc[w][1], acc[w][2], acc[w][3],
                    a0, a1, a2, a3, b0, b1);
        }
    }

    #pragma unroll
    for (int rh = 0; rh < 2; rh++) {
        #pragma unroll
        for (int cp = 0; cp < 2; cp++) {
            int h = mi * 16 + gid + rh * 8;
            int c = cBase + nh * 8 + tig * 2 + cp;
            size_t base = ((size_t)(b * NC + c) * NH + h) * NW + w0 + wh * 4;
            uint2 o;
            o.x = pack_h2(acc[0][rh * 2 + cp], acc[1][rh * 2 + cp]);
            o.y = pack_h2(acc[2][rh * 2 + cp], acc[3][rh * 2 + cp]);
            *reinterpret_cast<uint2*>(od + base) = o;
        }
    }
}

// ---------------------------------------------------------------------------
// aggW_f16 (R14, measured 40us): fp16 partials -> outW.
// ---------------------------------------------------------------------------
__global__ void __launch_bounds__(512)
aggW_f16(const __half* __restrict__ v2, const __half* __restrict__ v1,
         const __half* __restrict__ atth, __half* __restrict__ outw)
{
    __shared__ alignas(16) uint32_t Ast[64 * 36];
    __shared__ alignas(16) uint32_t Vst[128 * 36];

    const int t  = threadIdx.x;
    const int h  = blockIdx.x;
    const int cs = blockIdx.y;
    const int b  = blockIdx.z;
    const int s  = cs >> 2;
    const int cBase = (cs & 3) * 128;

    const __half* v = s ? v1 : v2;
    __half* od = outw + (size_t)s * NB * NC * HWP;

    {
        int f = t;
        int r = f >> 3, q8 = f & 7;
        cp_async16(Ast + r * 36 + q8 * 4,
                   atth + (((size_t)(b * NH + h) * NW) + r) * 128 + 64 + q8 * 8);
    }
    #pragma unroll
    for (int i = 0; i < 2; i++) {
        int f = t + i * 512;
        int r = f >> 3, q8 = f & 7;
        cp_async16(Vst + r * 36 + q8 * 4,
                   v + (((size_t)(b * NC + cBase + r) * NH) + h) * NW + q8 * 8);
    }
    CP_COMMIT();
    CP_WAIT0();
    __syncthreads();

    const int warp = t >> 5, lane = t & 31;
    const int gid = lane >> 2, tig = lane & 3;
    const int mi = warp >> 2;
    const int nq = warp & 3;

    float acc[4][4];
    #pragma unroll
    for (int ni = 0; ni < 4; ni++)
        #pragma unroll
        for (int r = 0; r < 4; r++) acc[ni][r] = 0.f;

    #pragma unroll
    for (int k = 0; k < 4; k++) {
        const int kk2 = k * 8;
        const int m = mi * 16;
        uint32_t a0 = Ast[(m + gid    ) * 36 + kk2 + tig    ];
        uint32_t a1 = Ast[(m + gid + 8) * 36 + kk2 + tig    ];
        uint32_t a2 = Ast[(m + gid    ) * 36 + kk2 + tig + 4];
        uint32_t a3 = Ast[(m + gid + 8) * 36 + kk2 + tig + 4];
        #pragma unroll
        for (int ni = 0; ni < 4; ni++) {
            int n = nq * 32 + ni * 8 + gid;
            uint32_t b0 = Vst[n * 36 + kk2 + tig    ];
            uint32_t b1 = Vst[n * 36 + kk2 + tig + 4];
            mma_f16(acc[ni][0], acc[ni][1], acc[ni][2], acc[ni][3],
                    a0, a1, a2, a3, b0, b1);
        }
    }

    #pragma unroll
    for (int ni = 0; ni < 4; ni++) {
        #pragma unroll
        for (int rh = 0; rh < 2; rh++) {
            int w = mi * 16 + gid + rh * 8;
            #pragma unroll
            for (int cp = 0; cp < 2; cp++) {
                int c = cBase + nq * 32 + ni * 8 + tig * 2 + cp;
                size_t idx = ((size_t)(b * NC + c) * NH + h) * NW + w;
                od[idx] = __float2half(acc[ni][rh * 2 + cp]);
            }
        }
    }
}

// ---------------------------------------------------------------------------
// combine: y = x + g*(outH + outW) (R15, streaming).
// ---------------------------------------------------------------------------
__global__ void __launch_bounds__(512)
combine_kernel(const float* __restrict__ x2, const float* __restrict__ x1,
               const __half* __restrict__ outh, const __half* __restrict__ outw,
               const float* __restrict__ gamma, float* __restrict__ y)
{
    const size_t N = (size_t)NB * NC * HWP;
    const int sIdx = blockIdx.y;
    const float* x = sIdx ? x1 : x2;
    const __half* oh = outh + sIdx * N;
    const __half* ow = outw + sIdx * N;
    float* yd = y + sIdx * N;
    const float g = gamma[0];

    size_t i = ((size_t)blockIdx.x * 512 + threadIdx.x) * 8;

    float4 xa = *reinterpret_cast<const float4*>(x + i);
    float4 xb = *reinterpret_cast<const float4*>(x + i + 4);
    uint4 hu = *reinterpret_cast<const uint4*>(oh + i);
    uint4 wu = *reinterpret_cast<const uint4*>(ow + i);

    float2 h0 = __half22float2(*reinterpret_cast<__half2*>(&hu.x));
    float2 h1 = __half22float2(*reinterpret_cast<__half2*>(&hu.y));
    float2 h2 = __half22float2(*reinterpret_cast<__half2*>(&hu.z));
    float2 h3 = __half22float2(*reinterpret_cast<__half2*>(&hu.w));
    float2 w0 = __half22float2(*reinterpret_cast<__half2*>(&wu.x));
    float2 w1 = __half22float2(*reinterpret_cast<__half2*>(&wu.y));
    float2 w2 = __half22float2(*reinterpret_cast<__half2*>(&wu.z));
    float2 w3 = __half22float2(*reinterpret_cast<__half2*>(&wu.w));

    float4 oa, ob;
    oa.x = xa.x + g * (h0.x + w0.x);
    oa.y = xa.y + g * (h0.y + w0.y);
    oa.z = xa.z + g * (h1.x + w1.x);
    oa.w = xa.w + g * (h1.y + w1.y);
    ob.x = xb.x + g * (h2.x + w2.x);
    ob.y = xb.y + g * (h2.y + w2.y);
    ob.z = xb.z + g * (h3.x + w3.x);
    ob.w = xb.w + g * (h3.y + w3.y);

    *reinterpret_cast<float4*>(yd + i)     = oa;
    *reinterpret_cast<float4*>(yd + i + 4) = ob;
}

// ---------------------------------------------------------------------------
extern "C" void kernel_launch(void* const* d_in, const int* in_sizes, int n_in,
                              void* d_out, int out_size)
{
    const float* x2    = (const float*)d_in[0];
    const float* x1    = (const float*)d_in[1];
    const float* q_w   = (const float*)d_in[2];
    const float* q_b   = (const float*)d_in[3];
    const float* k_w   = (const float*)d_in[4];
    const float* k_b   = (const float*)d_in[5];
    const float* v_w   = (const float*)d_in[6];
    const float* v_b   = (const float*)d_in[7];
    const float* gamma = (const float*)d_in[8];
    float* y = (float*)d_out;

    float *gq, *gk, *gatt;
    __half *gv2, *gv1, *gatth, *gouth, *goutw;
    cudaGetSymbolAddress((void**)&gq,    g_q);
    cudaGetSymbolAddress((void**)&gk,    g_k);
    cudaGetSymbolAddress((void**)&gv2,   g_v2h);
    cudaGetSymbolAddress((void**)&gv1,   g_v1h);
    cudaGetSymbolAddress((void**)&gatt,  g_att);
    cudaGetSymbolAddress((void**)&gatth, g_atth);
    cudaGetSymbolAddress((void**)&gouth, g_outh);
    cudaGetSymbolAddress((void**)&goutw, g_outw);

    cudaFuncSetAttribute(aggH_f16, cudaFuncAttributeMaxDynamicSharedMemorySize, AGH_SMEM);

    // Launch order: ncu capture slot = 4th launch = gemm_v (new kernel).
    preconv<<<640, 256>>>(v_w, q_w, k_w);
    gemm_qk<<<dim3(32, 1, 8), 256>>>(q_b, k_b, x2, gq, gk);
    energy_HW<<<dim3(64, 2, NB), 256>>>(gq, gk, gatt);
    gemm_v<<<dim3(32, 2, 16), 512>>>(v_b, x2, x1, gv2, gv1);
    softmax_kernel<<<(NB * HWP) / 8, 256>>>(gatt, gatth);
    aggH_f16<<<dim3(8, 64, NB), 512, AGH_SMEM>>>(gv2, gv1, gatth, gouth);
    aggW_f16<<<dim3(NH, 8, NB), 512>>>(gv2, gv1, gatth, goutw);
    combine_kernel<<<dim3(4096, 2), 512>>>(x2, x1, gouth, goutw, gamma, y);
}